// round 11
// baseline (speedup 1.0000x reference)
#include <cuda_runtime.h>
#include <math_constants.h>

#define H 1024
#define S 32768
#define ROWS_PER_BLK 8
#define SCORE_GRID (S / ROWS_PER_BLK)    // 4096
#define NSLICES 64                       // v partials: 16 d-rows per slice

// Scratch (no allocations allowed)
__device__ float g_vpart[NSLICES * H];   // 256 KB
__device__ float g_v[H];
__device__ float g_scores[S];
__device__ float g_bmax[SCORE_GRID];
__device__ float g_bsum[SCORE_GRID];
__device__ float g_M;
__device__ float g_inv;
__device__ unsigned g_cnt1;              // zero-init; self-resetting
__device__ unsigned g_cnt2;

// ---------------------------------------------------------------------------
// K1: v = W^T hidden in a single kernel.
// 64 blocks x 256 thr stream W (4 MB, coalesced); last-finishing block
// reduces the 64 partials per h in fixed order (deterministic).
// ---------------------------------------------------------------------------
__global__ __launch_bounds__(256) void v_kernel(const float* __restrict__ W,
                                                const float* __restrict__ hidden) {
    __shared__ unsigned s_last;
    const int tid = threadIdx.x;
    const int b   = blockIdx.x;

    // partials for 16 d-rows
    {
        const int d0 = b * (H / NSLICES);
        float acc0 = 0.f, acc1 = 0.f, acc2 = 0.f, acc3 = 0.f;
#pragma unroll
        for (int dd = 0; dd < H / NSLICES; dd++) {
            const float hd = __ldg(&hidden[d0 + dd]);
            const float* wr = W + (size_t)(d0 + dd) * H;
            acc0 += wr[tid      ] * hd;
            acc1 += wr[tid + 256] * hd;
            acc2 += wr[tid + 512] * hd;
            acc3 += wr[tid + 768] * hd;
        }
        g_vpart[b * H + tid      ] = acc0;
        g_vpart[b * H + tid + 256] = acc1;
        g_vpart[b * H + tid + 512] = acc2;
        g_vpart[b * H + tid + 768] = acc3;
    }

    __threadfence();
    __syncthreads();
    if (tid == 0) {
        unsigned prev = atomicAdd(&g_cnt1, 1u);
        s_last = (prev == (unsigned)gridDim.x - 1u) ? 1u : 0u;
    }
    __syncthreads();

    if (s_last) {
        __threadfence();
        // thread tid reduces float4 column tid: h = 4*tid .. 4*tid+3
        const float4* vp4 = reinterpret_cast<const float4*>(g_vpart);
        float4 a = make_float4(0.f, 0.f, 0.f, 0.f);
#pragma unroll 8
        for (int i = 0; i < NSLICES; i++) {
            float4 p = vp4[i * (H / 4) + tid];
            a.x += p.x; a.y += p.y; a.z += p.z; a.w += p.w;
        }
        reinterpret_cast<float4*>(g_v)[tid] = a;
        if (tid == 0) { g_cnt1 = 0; __threadfence(); }
    }
}

// ---------------------------------------------------------------------------
// K2: scores = enc . v   (the 128 MB stream, R2 structure: proven ~5.8 TB/s)
// 4096 blocks x 256 thr, warp per row, 8 float4 in flight per warp.
// Emits per-block (max, expsum); last-finishing block reduces the 4096
// pairs in fixed order -> g_M, g_inv.
// ---------------------------------------------------------------------------
__global__ __launch_bounds__(256) void scores_kernel(const float* __restrict__ enc) {
    __shared__ float sv[H];
    __shared__ float s_sc[ROWS_PER_BLK];
    __shared__ float red[256];
    __shared__ unsigned s_last;

    const int tid  = threadIdx.x;
    const int warp = tid >> 5;
    const int lane = tid & 31;
    const int b    = blockIdx.x;

    // stage v into shared (256 x float4)
    reinterpret_cast<float4*>(sv)[tid] = reinterpret_cast<const float4*>(g_v)[tid];
    __syncthreads();

    const size_t row = (size_t)b * ROWS_PER_BLK + warp;
    const float4* r  = reinterpret_cast<const float4*>(enc + row * H);
    const float4* v4 = reinterpret_cast<const float4*>(sv);

    float acc = 0.f;
#pragma unroll
    for (int k = 0; k < 8; k++) {
        float4 e  = r[lane + k * 32];
        float4 vv = v4[lane + k * 32];
        acc += e.x * vv.x + e.y * vv.y + e.z * vv.z + e.w * vv.w;
    }
#pragma unroll
    for (int o = 16; o > 0; o >>= 1) acc += __shfl_xor_sync(0xFFFFFFFFu, acc, o);

    if (lane == 0) {
        g_scores[row] = acc;
        s_sc[warp] = acc;
    }
    __syncthreads();

    // warp 0: block (max, expsum) over 8 row-scores
    if (tid == 0) {
        float m = s_sc[0];
#pragma unroll
        for (int i = 1; i < ROWS_PER_BLK; i++) m = fmaxf(m, s_sc[i]);
        float s = 0.f;
#pragma unroll
        for (int i = 0; i < ROWS_PER_BLK; i++) s += __expf(s_sc[i] - m);
        g_bmax[b] = m;
        g_bsum[b] = s;
        __threadfence();
        unsigned prev = atomicAdd(&g_cnt2, 1u);
        s_last = (prev == (unsigned)gridDim.x - 1u) ? 1u : 0u;
    }
    __syncthreads();

    // last-finishing block: fixed-order reduce of all 4096 pairs
    if (s_last) {
        __threadfence();
        float pm[SCORE_GRID / 256], ps[SCORE_GRID / 256];
        float m = -CUDART_INF_F;
#pragma unroll
        for (int k = 0; k < SCORE_GRID / 256; k++) {
            pm[k] = g_bmax[tid + k * 256];
            ps[k] = g_bsum[tid + k * 256];
            m = fmaxf(m, pm[k]);
        }
        red[tid] = m;
        __syncthreads();
#pragma unroll
        for (int s = 128; s > 0; s >>= 1) {
            if (tid < s) red[tid] = fmaxf(red[tid], red[tid + s]);
            __syncthreads();
        }
        const float M = red[0];
        __syncthreads();

        float sum = 0.f;
#pragma unroll
        for (int k = 0; k < SCORE_GRID / 256; k++)
            sum += ps[k] * __expf(pm[k] - M);
        red[tid] = sum;
        __syncthreads();
#pragma unroll
        for (int s = 128; s > 0; s >>= 1) {
            if (tid < s) red[tid] += red[tid + s];
            __syncthreads();
        }
        if (tid == 0) {
            g_M = M;
            g_inv = 1.0f / red[0];
            g_cnt2 = 0;
            __threadfence();
        }
    }
}

// ---------------------------------------------------------------------------
// K3: float4 normalize. 64 blocks x 128 thr, 1 float4 per thread.
// ---------------------------------------------------------------------------
__global__ __launch_bounds__(128) void normalize_kernel(float* __restrict__ out) {
    const int i = blockIdx.x * 128 + threadIdx.x;       // float4 index
    const float M = g_M;
    const float inv = g_inv;
    float4 s = reinterpret_cast<const float4*>(g_scores)[i];
    float4 o;
    o.x = __expf(s.x - M) * inv;
    o.y = __expf(s.y - M) * inv;
    o.z = __expf(s.z - M) * inv;
    o.w = __expf(s.w - M) * inv;
    reinterpret_cast<float4*>(out)[i] = o;
}

// ---------------------------------------------------------------------------
extern "C" void kernel_launch(void* const* d_in, const int* in_sizes, int n_in,
                              void* d_out, int out_size) {
    const float* hidden = (const float*)d_in[0];   // [H]
    const float* enc    = (const float*)d_in[1];   // [S, H]
    const float* W      = (const float*)d_in[2];   // [H, H]
    float* out          = (float*)d_out;           // [S]

    v_kernel<<<NSLICES, 256>>>(W, hidden);
    scores_kernel<<<SCORE_GRID, 256>>>(enc);
    normalize_kernel<<<S / 4 / 128, 128>>>(out);
}

// round 13
// speedup vs baseline: 1.2313x; 1.2313x over previous
#include <cuda_runtime.h>
#include <math_constants.h>

#define H 1024
#define S 32768
#define GRID 256
#define BLK 256
#define ROWS_PER_BLK (S / GRID)          // 128
#define TILE_ROWS 8
#define NTILES (ROWS_PER_BLK / TILE_ROWS) // 16
#define STAGES 3
#define TILE_BYTES (TILE_ROWS * H * 4)    // 32768
#define TILE_F4 (TILE_ROWS * H / 4)       // 2048
#define SMEM_DYN (STAGES * TILE_BYTES)    // 98304
#define NSLICES 256                       // P0: 4 d-rows per slice (all blocks)

// Scratch (no allocations allowed)
__device__ float g_vpart[NSLICES * H];    // 1 MB
__device__ float g_bmax[GRID];
__device__ float g_bsum[GRID];
__device__ float g_v[H];
__device__ unsigned g_bar;   // zero-init; self-resetting
__device__ unsigned g_done;

__device__ __forceinline__ void grid_sync(unsigned target) {
    __syncthreads();
    __threadfence();
    if (threadIdx.x == 0) {
        atomicAdd(&g_bar, 1u);
        while (*(volatile unsigned*)&g_bar < target) __nanosleep(64);
    }
    __syncthreads();
}

__device__ __forceinline__ void mbar_wait(unsigned mbar, unsigned parity) {
    asm volatile(
        "{\n\t"
        ".reg .pred P;\n\t"
        "W_%=:\n\t"
        "mbarrier.try_wait.parity.acquire.cta.shared::cta.b64 P, [%0], %1, 0x989680;\n\t"
        "@P bra D_%=;\n\t"
        "bra W_%=;\n\t"
        "D_%=:\n\t"
        "}" :: "r"(mbar), "r"(parity) : "memory");
}

__global__ __launch_bounds__(BLK, 2) void fused_kernel(
    const float* __restrict__ W,
    const float* __restrict__ hidden,
    const float* __restrict__ enc,
    float* __restrict__ out)
{
    extern __shared__ float4 tile[];                   // [STAGES][TILE_F4]
    __shared__ __align__(8) unsigned long long mbar[STAGES];
    __shared__ float s_sc[ROWS_PER_BLK];
    __shared__ float red[BLK];

    const int tid  = threadIdx.x;
    const int warp = tid >> 5;
    const int lane = tid & 31;
    const int b    = blockIdx.x;

    // mbarrier init (count=1; producer arrives via expect_tx)
    if (tid == 0) {
#pragma unroll
        for (int s = 0; s < STAGES; s++) {
            unsigned a = (unsigned)__cvta_generic_to_shared(&mbar[s]);
            asm volatile("mbarrier.init.shared.b64 [%0], 1;" :: "r"(a) : "memory");
        }
        asm volatile("fence.proxy.async.shared::cta;" ::: "memory");
    }

    // ---------------- P0: v partials — ALL 256 blocks, 4 d-rows each -------
    // 16 fully-unrolled independent W loads per thread -> whole 4 MB in flight.
    {
        const int d0 = b * 4;
        float acc0 = 0.f, acc1 = 0.f, acc2 = 0.f, acc3 = 0.f;
#pragma unroll
        for (int dd = 0; dd < 4; dd++) {
            const float hd = hidden[d0 + dd];
            const float* wr = W + (size_t)(d0 + dd) * H;
            acc0 += wr[tid      ] * hd;
            acc1 += wr[tid + 256] * hd;
            acc2 += wr[tid + 512] * hd;
            acc3 += wr[tid + 768] * hd;
        }
        g_vpart[b * H + tid      ] = acc0;
        g_vpart[b * H + tid + 256] = acc1;
        g_vpart[b * H + tid + 512] = acc2;
        g_vpart[b * H + tid + 768] = acc3;
    }
    grid_sync(GRID);

    // ---------------- P1: reduce 256 partials -> g_v (blocks 0..127) -------
    // warp per h; lane sums 8 slices (independent 4 KB-strided L2 loads).
    if (b < 128) {
        const int h = b * 8 + warp;
        float a0 = g_vpart[(lane      ) * H + h];
        float a1 = g_vpart[(lane +  32) * H + h];
        float a2 = g_vpart[(lane +  64) * H + h];
        float a3 = g_vpart[(lane +  96) * H + h];
        float a4 = g_vpart[(lane + 128) * H + h];
        float a5 = g_vpart[(lane + 160) * H + h];
        float a6 = g_vpart[(lane + 192) * H + h];
        float a7 = g_vpart[(lane + 224) * H + h];
        float a = ((a0 + a1) + (a2 + a3)) + ((a4 + a5) + (a6 + a7));
#pragma unroll
        for (int o = 16; o > 0; o >>= 1) a += __shfl_xor_sync(0xFFFFFFFFu, a, o);
        if (lane == 0) g_v[h] = a;
    }
    grid_sync(2 * GRID);

    // ---------------- P2: stream enc via cp.async.bulk pipeline ------------
    float4 vr[8];
    const float4* v4 = reinterpret_cast<const float4*>(g_v);
#pragma unroll
    for (int k = 0; k < 8; k++) vr[k] = v4[lane + k * 32];

    const char* src_base = reinterpret_cast<const char*>(enc)
                         + (size_t)b * ROWS_PER_BLK * H * 4;

    if (tid == 0) {
#pragma unroll
        for (int s = 0; s < STAGES; s++) {
            unsigned ba = (unsigned)__cvta_generic_to_shared(&mbar[s]);
            unsigned da = (unsigned)__cvta_generic_to_shared(tile + s * TILE_F4);
            asm volatile("mbarrier.arrive.expect_tx.shared.b64 _, [%0], %1;"
                         :: "r"(ba), "r"(TILE_BYTES) : "memory");
            asm volatile("cp.async.bulk.shared::cta.global.mbarrier::complete_tx::bytes "
                         "[%0], [%1], %2, [%3];"
                         :: "r"(da), "l"(src_base + (size_t)s * TILE_BYTES),
                            "r"(TILE_BYTES), "r"(ba) : "memory");
        }
    }

#pragma unroll 1
    for (int t = 0; t < NTILES; t++) {
        const int st = t % STAGES;
        unsigned ba = (unsigned)__cvta_generic_to_shared(&mbar[st]);
        mbar_wait(ba, (t / STAGES) & 1);

        const float4* rowp = tile + st * TILE_F4 + warp * (H / 4);
        float acc = 0.f;
#pragma unroll
        for (int k = 0; k < 8; k++) {
            float4 e = rowp[lane + k * 32];
            acc += e.x * vr[k].x + e.y * vr[k].y + e.z * vr[k].z + e.w * vr[k].w;
        }
#pragma unroll
        for (int o = 16; o > 0; o >>= 1) acc += __shfl_xor_sync(0xFFFFFFFFu, acc, o);
        if (lane == 0) s_sc[t * TILE_ROWS + warp] = acc;

        __syncthreads();   // all warps done reading stage st
        if (tid == 0 && t + STAGES < NTILES) {
            unsigned da = (unsigned)__cvta_generic_to_shared(tile + st * TILE_F4);
            asm volatile("mbarrier.arrive.expect_tx.shared.b64 _, [%0], %1;"
                         :: "r"(ba), "r"(TILE_BYTES) : "memory");
            asm volatile("cp.async.bulk.shared::cta.global.mbarrier::complete_tx::bytes "
                         "[%0], [%1], %2, [%3];"
                         :: "r"(da), "l"(src_base + (size_t)(t + STAGES) * TILE_BYTES),
                            "r"(TILE_BYTES), "r"(ba) : "memory");
        }
    }

    // block (max, expsum) over its 128 scores
    red[tid] = (tid < ROWS_PER_BLK) ? s_sc[tid] : -CUDART_INF_F;
    __syncthreads();
#pragma unroll
    for (int s = 128; s > 0; s >>= 1) {
        if (tid < s) red[tid] = fmaxf(red[tid], red[tid + s]);
        __syncthreads();
    }
    const float Mb = red[0];
    __syncthreads();
    red[tid] = (tid < ROWS_PER_BLK) ? __expf(s_sc[tid] - Mb) : 0.f;
    __syncthreads();
#pragma unroll
    for (int s = 128; s > 0; s >>= 1) {
        if (tid < s) red[tid] += red[tid + s];
        __syncthreads();
    }
    if (tid == 0) {
        g_bmax[b] = Mb;
        g_bsum[b] = red[0];
    }
    grid_sync(3 * GRID);

    // ---------------- P3: redundant pair-reduce + normalize ----------------
    const float pm = g_bmax[tid];          // GRID == BLK == 256
    const float ps = g_bsum[tid];
    red[tid] = pm;
    __syncthreads();
#pragma unroll
    for (int s = 128; s > 0; s >>= 1) {
        if (tid < s) red[tid] = fmaxf(red[tid], red[tid + s]);
        __syncthreads();
    }
    const float M = red[0];
    __syncthreads();
    red[tid] = ps * __expf(pm - M);
    __syncthreads();
#pragma unroll
    for (int s = 128; s > 0; s >>= 1) {
        if (tid < s) red[tid] += red[tid + s];
        __syncthreads();
    }
    const float inv = 1.0f / red[0];

    if (tid < ROWS_PER_BLK)
        out[b * ROWS_PER_BLK + tid] = __expf(s_sc[tid] - M) * inv;

    // ---------------- reset counters for next graph replay ------------------
    __threadfence();
    __syncthreads();
    if (tid == 0) {
        unsigned d = atomicAdd(&g_done, 1u) + 1;
        if (d == GRID) {
            g_bar = 0;
            g_done = 0;
            __threadfence();
        }
    }
}

// ---------------------------------------------------------------------------
extern "C" void kernel_launch(void* const* d_in, const int* in_sizes, int n_in,
                              void* d_out, int out_size) {
    const float* hidden = (const float*)d_in[0];   // [H]
    const float* enc    = (const float*)d_in[1];   // [S, H]
    const float* W      = (const float*)d_in[2];   // [H, H]
    float* out          = (float*)d_out;           // [S]

    cudaFuncSetAttribute(fused_kernel,
                         cudaFuncAttributeMaxDynamicSharedMemorySize, SMEM_DYN);
    fused_kernel<<<GRID, BLK, SMEM_DYN>>>(W, hidden, enc, out);
}